// round 8
// baseline (speedup 1.0000x reference)
#include <cuda_runtime.h>
#include <math.h>

#define NG      4
#define HIDN    64
#define BATCH   4096
#define TSTEPS  128
#define NB      32
#define NTHREADS 256
#define NTILES  (BATCH / NB)     // 128
#define GRIDSZ  (NG * NTILES)    // 512

typedef unsigned long long u64;

// ---------------- global scratch (allocation-free) ----------------
__device__ float g_ll[(size_t)NG * TSTEPS * BATCH];
__device__ float g_xn[(size_t)NG * TSTEPS * 6 * BATCH];
__device__ float g_W0[(size_t)NG * 112 * 256];   // interleaved LSTM0 weights

// ---------------- f32x2 helpers ----------------
__device__ __forceinline__ u64 dup2(float a) {
    u64 r; asm("mov.b64 %0, {%1, %1};" : "=l"(r) : "f"(a)); return r;
}
__device__ __forceinline__ void unpk2(u64 v, float& lo, float& hi) {
    asm("mov.b64 {%0, %1}, %2;" : "=f"(lo), "=f"(hi) : "l"(v));
}
__device__ __forceinline__ u64 fma2(u64 a, u64 b, u64 c) {
    u64 d; asm("fma.rn.f32x2 %0, %1, %2, %3;" : "=l"(d) : "l"(a), "l"(b), "l"(c));
    return d;
}

// ---------------- fast activations ----------------
__device__ __forceinline__ float sigf(float x) {
    return __fdividef(1.0f, 1.0f + __expf(-x));
}
__device__ __forceinline__ float tanh_fast(float x) {
    return 1.0f - 2.0f * __fdividef(1.0f, __expf(2.0f * x) + 1.0f);
}

// batch -> float offset in a dup'd 72-float row
__device__ __forceinline__ int doff(int b) { return 2 * b + ((b >= 16) ? 4 : 0); }

struct __align__(16) Smem {
    float We1[19 * 48];
    float be1[48];
    float We2[48 * 48];
    float be2[48];
    float b0[256];          // [u*4+gate]
    float W1[68 * 16];
    float b1[16];
    float inTd[112 * 72];   // dup'd rows: 0..47 e2, 48..111 h0
    float e1Td[48 * 72];    // dup'd
    float c0T[64 * 32];
    float featsT[19 * 32];
    float g1T[16 * 32];
    float h1T[4 * 32];
    float c1T[4 * 32];
    float zsT[2][4 * 32];   // double-buffered
    float xT[6 * 32];
    float PT[36 * 32];
};

// ---- 4x4 LU (no pivot) with precomputed reciprocals ----
__device__ __forceinline__ void lu4_fact(float* M, float* id) {
    id[0] = __fdividef(1.0f, M[0]);
    M[4] *= id[0]; M[8] *= id[0]; M[12] *= id[0];
    M[5]  -= M[4]  * M[1]; M[6]  -= M[4]  * M[2]; M[7]  -= M[4]  * M[3];
    M[9]  -= M[8]  * M[1]; M[10] -= M[8]  * M[2]; M[11] -= M[8]  * M[3];
    M[13] -= M[12] * M[1]; M[14] -= M[12] * M[2]; M[15] -= M[12] * M[3];
    id[1] = __fdividef(1.0f, M[5]);
    M[9] *= id[1]; M[13] *= id[1];
    M[10] -= M[9]  * M[6]; M[11] -= M[9]  * M[7];
    M[14] -= M[13] * M[6]; M[15] -= M[13] * M[7];
    id[2] = __fdividef(1.0f, M[10]);
    M[14] *= id[2];
    M[15] -= M[14] * M[11];
    id[3] = __fdividef(1.0f, M[15]);
}
__device__ __forceinline__ void lu4_solve(const float* M, const float* id,
                                          const float* r, float* v) {
    float y0 = r[0];
    float y1 = r[1] - M[4]  * y0;
    float y2 = r[2] - M[8]  * y0 - M[9]  * y1;
    float y3 = r[3] - M[12] * y0 - M[13] * y1 - M[14] * y2;
    v[3] = y3 * id[3];
    v[2] = (y2 - M[11] * v[3]) * id[2];
    v[1] = (y1 - M[6] * v[2] - M[7] * v[3]) * id[1];
    v[0] = (y0 - M[1] * v[1] - M[2] * v[2] - M[3] * v[3]) * id[0];
}
__device__ __forceinline__ void lu4_solveT(const float* M, const float* id,
                                           const float* r, float* v) {
    float w0 = r[0] * id[0];
    float w1 = (r[1] - M[1] * w0) * id[1];
    float w2 = (r[2] - M[2] * w0 - M[6]  * w1) * id[2];
    float w3 = (r[3] - M[3] * w0 - M[7]  * w1 - M[11] * w2) * id[3];
    v[3] = w3;
    v[2] = w2 - M[14] * v[3];
    v[1] = w1 - M[9]  * v[2] - M[13] * v[3];
    v[0] = w0 - M[4]  * v[1] - M[8]  * v[2] - M[12] * v[3];
}

// ---------------- prep: interleave W0 into global scratch ----------------
__global__ void nkf_prep(const float* __restrict__ Wi0, const float* __restrict__ Wh0)
{
    int i = blockIdx.x * blockDim.x + threadIdx.x;
    if (i >= NG * 112 * 256) return;
    int g = i / (112 * 256);
    int r = i % (112 * 256);
    int k = r >> 8, col = r & 255;
    int u = col >> 2, gate = col & 3;
    int sc = gate * 64 + u;
    g_W0[i] = (k < 48) ? Wi0[(g * 48 + k) * 256 + sc]
                       : Wh0[(g * 64 + (k - 48)) * 256 + sc];
}

__global__ __launch_bounds__(NTHREADS, 2)
void nkf_main(const float* __restrict__ z,    const float* __restrict__ x0,
              const float* __restrict__ We1,  const float* __restrict__ be1,
              const float* __restrict__ We2,  const float* __restrict__ be2,
              const float* __restrict__ Wi0,  const float* __restrict__ Wh0,
              const float* __restrict__ b0g,  const float* __restrict__ Wi1,
              const float* __restrict__ Wh1,  const float* __restrict__ b1l,
              const float* __restrict__ Qlog, const float* __restrict__ Rlog)
{
    extern __shared__ __align__(16) char smem_raw[];
    Smem& s = *reinterpret_cast<Smem*>(smem_raw);

    const int tid  = threadIdx.x;
    const int g    = blockIdx.x / NTILES;
    const int tile = blockIdx.x % NTILES;
    const int gb0  = tile * NB;
    const int b    = tid & 31;
    const int w    = tid >> 5;
    const int cg   = tid >> 3;   // 0..31 (column group: 8 cols = 2 units)
    const int bg   = tid & 7;    // 0..7  (batch group: 4 batch)

    // ---------------- stage weights (W0 lives in g_W0 now) ----------------
    for (int i = tid; i < 19 * 48; i += NTHREADS) s.We1[i] = We1[i];
    for (int i = tid; i < 48;      i += NTHREADS) { s.be1[i] = be1[i]; s.be2[i] = be2[i]; }
    for (int i = tid; i < 48 * 48; i += NTHREADS) s.We2[i] = We2[i];
    for (int i = tid; i < 256; i += NTHREADS) {
        int u = i >> 2, gate = i & 3;
        s.b0[i] = b0g[g * 256 + gate * 64 + u];
    }
    for (int i = tid; i < 68 * 16; i += NTHREADS) {
        int k = i >> 4, j = i & 15;
        s.W1[i] = (k < 64) ? Wi1[(g * 64 + k) * 16 + j]
                           : Wh1[(g * 4 + (k - 64)) * 16 + j];
    }
    if (tid < 16) s.b1[tid] = b1l[g * 16 + tid];

    // noise diagonals (registers)
    float qd[6], rd[4];
#pragma unroll
    for (int i = 0; i < 6; i++) qd[i] = expf(Qlog[g * 6 + i]);
#pragma unroll
    for (int i = 0; i < 4; i++) rd[i] = expf(Rlog[i]);

    // ---------------- init state ----------------
    for (int i = tid; i < 6 * NB; i += NTHREADS) {
        int r = i >> 5, bb = i & 31;
        s.xT[i] = x0[(gb0 + bb) * 6 + r];
    }
    for (int i = tid; i < 36 * NB; i += NTHREADS) {
        int rc = i >> 5;
        s.PT[i] = (rc % 7 == 0) ? 1000.0f : 0.0f;
    }
    for (int i = tid; i < 64 * 32;  i += NTHREADS) s.c0T[i] = 0.0f;
    for (int i = tid; i < 112 * 72; i += NTHREADS) s.inTd[i] = 0.0f;
    for (int i = tid; i < 4 * 32;   i += NTHREADS) { s.h1T[i] = 0.0f; s.c1T[i] = 0.0f; }
    if (tid < 128) {
        int bb = tid >> 2, c = tid & 3;
        s.zsT[0][c * 32 + bb] = z[((gb0 + bb) * TSTEPS + 0) * 4 + c];
    }
    __syncthreads();

    // per-thread act-row base (float offset) for packed matvecs
    const int abase = (bg < 4) ? bg * 8 : bg * 8 + 4;
    const float* __restrict__ W0g = g_W0 + (size_t)g * (112 * 256);

    for (int t = 0; t < TSTEPS; ++t) {
        const float* zcur = s.zsT[t & 1];

        // ---- feats (warp 0) ----
        if (tid < 32) {
            float xv[6], zc[4], inn[4];
#pragma unroll
            for (int i = 0; i < 6; i++) xv[i] = s.xT[i * 32 + b];
#pragma unroll
            for (int c = 0; c < 4; c++) zc[c] = zcur[c * 32 + b];
            float n1 = 0.0f;
#pragma unroll
            for (int c = 0; c < 4; c++) { inn[c] = zc[c] - xv[c]; n1 += inn[c] * inn[c]; }
            n1 = sqrtf(fmaxf(n1, 0.0f));
            float np = sqrtf(fmaxf(xv[0]*xv[0] + xv[1]*xv[1] + xv[2]*xv[2], 0.0f));
            float nv = sqrtf(fmaxf(xv[3]*xv[3] + xv[4]*xv[4] + xv[5]*xv[5], 0.0f));
#pragma unroll
            for (int c = 0; c < 4; c++) s.featsT[c * 32 + b] = zc[c];
#pragma unroll
            for (int i = 0; i < 6; i++) s.featsT[(4 + i) * 32 + b] = xv[i];
#pragma unroll
            for (int c = 0; c < 4; c++) s.featsT[(10 + c) * 32 + b] = inn[c];
            s.featsT[14 * 32 + b] = n1;
            s.featsT[15 * 32 + b] = np;
            s.featsT[16 * 32 + b] = nv;
            s.featsT[17 * 32 + b] = (float)t / 100.0f;
            s.featsT[18 * 32 + b] = 1.0f;
        }
        __syncthreads();   // S2

        // ---- e1 = relu(feats @ We1 + be1), scalar, dup'd writes ----
        {
            float acc[6];
#pragma unroll
            for (int j = 0; j < 6; j++) acc[j] = s.be1[w * 6 + j];
            for (int k = 0; k < 19; k++) {
                float f = s.featsT[k * 32 + b];
#pragma unroll
                for (int j = 0; j < 6; j++) acc[j] += f * s.We1[k * 48 + w * 6 + j];
            }
            int o = doff(b);
#pragma unroll
            for (int j = 0; j < 6; j++)
                *(u64*)(s.e1Td + (w * 6 + j) * 72 + o) = dup2(fmaxf(acc[j], 0.0f));
        }
        __syncthreads();   // S3

        // ---- e2 = relu(e1 @ We2 + be2), packed col-pairs, -> inTd rows 0..47 ----
        if (tid < 192) {
            int cp  = tid >> 3;     // 0..23 (col pair)
            int bg2 = tid & 7;
            int ab  = (bg2 < 4) ? bg2 * 8 : bg2 * 8 + 4;
            u64 bias = *(const u64*)(s.be2 + cp * 2);
            u64 acc0 = bias, acc1 = bias, acc2 = bias, acc3 = bias;
            const float* wp = s.We2 + cp * 2;
            const float* ap = s.e1Td + ab;
#pragma unroll 4
            for (int k = 0; k < 48; k++) {
                u64 wv = *(const u64*)(wp);
                ulonglong2 p01 = *(const ulonglong2*)(ap);
                ulonglong2 p23 = *(const ulonglong2*)(ap + 4);
                acc0 = fma2(wv, p01.x, acc0);
                acc1 = fma2(wv, p01.y, acc1);
                acc2 = fma2(wv, p23.x, acc2);
                acc3 = fma2(wv, p23.y, acc3);
                wp += 48; ap += 72;
            }
            u64 av[4] = {acc0, acc1, acc2, acc3};
#pragma unroll
            for (int m = 0; m < 4; m++) {
                int bb = bg2 * 4 + m, o = doff(bb);
                float lo, hi; unpk2(av[m], lo, hi);
                *(u64*)(s.inTd + (2 * cp)     * 72 + o) = dup2(fmaxf(lo, 0.0f));
                *(u64*)(s.inTd + (2 * cp + 1) * 72 + o) = dup2(fmaxf(hi, 0.0f));
            }
        }
        __syncthreads();   // S4

        // ---- LSTM0 matvec: weights streamed from L2 (g_W0), acts from SMEM ----
        u64 a[16];
        {
#pragma unroll
            for (int p = 0; p < 4; p++) {
                u64 bias = *(const u64*)(s.b0 + cg * 8 + p * 2);
#pragma unroll
                for (int m = 0; m < 4; m++) a[p * 4 + m] = bias;
            }
            const float* wp = W0g + cg * 8;
            const float* ap = s.inTd + abase;
#pragma unroll 4
            for (int k = 0; k < 112; k++) {
                ulonglong2 w01 = __ldg((const ulonglong2*)(wp));
                ulonglong2 w23 = __ldg((const ulonglong2*)(wp + 4));
                ulonglong2 p01 = *(const ulonglong2*)(ap);
                ulonglong2 p23 = *(const ulonglong2*)(ap + 4);
                a[0]  = fma2(w01.x, p01.x, a[0]);
                a[1]  = fma2(w01.x, p01.y, a[1]);
                a[2]  = fma2(w01.x, p23.x, a[2]);
                a[3]  = fma2(w01.x, p23.y, a[3]);
                a[4]  = fma2(w01.y, p01.x, a[4]);
                a[5]  = fma2(w01.y, p01.y, a[5]);
                a[6]  = fma2(w01.y, p23.x, a[6]);
                a[7]  = fma2(w01.y, p23.y, a[7]);
                a[8]  = fma2(w23.x, p01.x, a[8]);
                a[9]  = fma2(w23.x, p01.y, a[9]);
                a[10] = fma2(w23.x, p23.x, a[10]);
                a[11] = fma2(w23.x, p23.y, a[11]);
                a[12] = fma2(w23.y, p01.x, a[12]);
                a[13] = fma2(w23.y, p01.y, a[13]);
                a[14] = fma2(w23.y, p23.x, a[14]);
                a[15] = fma2(w23.y, p23.y, a[15]);
                wp += 256; ap += 72;
            }
        }
        __syncthreads();   // S5: all reads of inTd done

        // ---- LSTM0 pointwise ----
        {
#pragma unroll
            for (int uu = 0; uu < 2; uu++) {
                int u = cg * 2 + uu;
#pragma unroll
                for (int m = 0; m < 4; m++) {
                    int bb = bg * 4 + m;
                    float gi, gf, gg, go;
                    unpk2(a[(uu * 2 + 0) * 4 + m], gi, gf);
                    unpk2(a[(uu * 2 + 1) * 4 + m], gg, go);
                    float cold = s.c0T[u * 32 + bb];
                    float cn = sigf(gf) * cold + sigf(gi) * tanh_fast(gg);
                    float hn = sigf(go) * tanh_fast(cn);
                    s.c0T[u * 32 + bb] = cn;
                    *(u64*)(s.inTd + (48 + u) * 72 + doff(bb)) = dup2(hn);
                }
            }
        }
        __syncthreads();   // S6: h0n ready

        // ---- LSTM1 matvec: 16 outs, 2 per thread ----
        {
            int o2 = doff(b);
            float a0 = s.b1[w], a1 = s.b1[w + 8];
            for (int k = 0; k < 64; k++) {
                float h = s.inTd[(48 + k) * 72 + o2];
                a0 += h * s.W1[k * 16 + w];
                a1 += h * s.W1[k * 16 + w + 8];
            }
#pragma unroll
            for (int k = 0; k < 4; k++) {
                float h = s.h1T[k * 32 + b];
                a0 += h * s.W1[(64 + k) * 16 + w];
                a1 += h * s.W1[(64 + k) * 16 + w + 8];
            }
            s.g1T[w * 32 + b] = a0;
            s.g1T[(w + 8) * 32 + b] = a1;
        }
        __syncthreads();   // S7

        // ---- LSTM1 pointwise ----
        if (tid < 128) {
            int u = tid >> 5;
            float gi = s.g1T[(0 + u)  * 32 + b];
            float gf = s.g1T[(4 + u)  * 32 + b];
            float gg = s.g1T[(8 + u)  * 32 + b];
            float go = s.g1T[(12 + u) * 32 + b];
            float cn = sigf(gf) * s.c1T[u * 32 + b] + sigf(gi) * tanh_fast(gg);
            float hn = sigf(go) * tanh_fast(cn);
            s.c1T[u * 32 + b] = cn;
            s.h1T[u * 32 + b] = hn;
        }
        __syncthreads();   // S8

        // ---- Kalman (warp 0) + z prefetch (warps 4-7) ----
        if (tid >= 128) {
            if (t + 1 < TSTEPS) {
                int q = tid - 128, bb = q >> 2, c = q & 3;
                s.zsT[(t + 1) & 1][c * 32 + bb] = z[((gb0 + bb) * TSTEPS + (t + 1)) * 4 + c];
            }
        } else if (tid < 32) {
            float logp = s.h1T[0 * 32 + b];
            float a0v = s.h1T[1 * 32 + b];
            float a1v = s.h1T[2 * 32 + b];
            float a2v = s.h1T[3 * 32 + b];

            float xv[6];
#pragma unroll
            for (int i = 0; i < 6; i++) xv[i] = s.xT[i * 32 + b];
            float xp[6];
            xp[0] = xv[0] + xv[3] + 0.5f * a0v;
            xp[1] = xv[1] + xv[4] + 0.5f * a1v;
            xp[2] = xv[2] + xv[5] + 0.5f * a2v;
            xp[3] = xv[3] + a0v;
            xp[4] = xv[4] + a1v;
            xp[5] = xv[5] + a2v;

            // P_pred = F P F^T + Q
            float Pp[36];
#pragma unroll
            for (int i = 0; i < 6; i++) {
#pragma unroll
                for (int j = 0; j < 6; j++) {
                    float v = s.PT[(i * 6 + j) * 32 + b];
                    if (i < 3) v += s.PT[((i + 3) * 6 + j) * 32 + b];
                    if (j < 3) {
                        v += s.PT[(i * 6 + j + 3) * 32 + b];
                        if (i < 3) v += s.PT[((i + 3) * 6 + j + 3) * 32 + b];
                    }
                    if (i == j) v += qd[i];
                    Pp[i * 6 + j] = v;
                }
            }

            float y[4];
#pragma unroll
            for (int c = 0; c < 4; c++) y[c] = zcur[c * 32 + b] - xp[c];

            float M[16];
#pragma unroll
            for (int r = 0; r < 4; r++)
#pragma unroll
                for (int c = 0; c < 4; c++)
                    M[r * 4 + c] = Pp[r * 6 + c] + ((r == c) ? rd[r] : 0.0f);
            float id[4];
            lu4_fact(M, id);
            float logdet = __logf(fabsf(M[0] * M[5] * M[10] * M[15]));

            float siy[4];
            lu4_solve(M, id, y, siy);

            float K[24];
#pragma unroll
            for (int i = 0; i < 6; i++) {
                float rhs[4] = { Pp[i * 6 + 0], Pp[i * 6 + 1], Pp[i * 6 + 2], Pp[i * 6 + 3] };
                lu4_solveT(M, id, rhs, &K[i * 4]);
            }

            float xn[6];
#pragma unroll
            for (int i = 0; i < 6; i++)
                xn[i] = xp[i] + K[i*4+0]*y[0] + K[i*4+1]*y[1] + K[i*4+2]*y[2] + K[i*4+3]*y[3];

#pragma unroll
            for (int i = 0; i < 6; i++) {
#pragma unroll
                for (int j = 0; j < 6; j++) {
                    float v = Pp[i * 6 + j]
                            - K[i*4+0] * Pp[0*6+j]
                            - K[i*4+1] * Pp[1*6+j]
                            - K[i*4+2] * Pp[2*6+j]
                            - K[i*4+3] * Pp[3*6+j];
                    s.PT[(i * 6 + j) * 32 + b] = v;
                }
            }

            float quad = y[0]*siy[0] + y[1]*siy[1] + y[2]*siy[2] + y[3]*siy[3];
            float ll = logp - 0.5f * (quad + logdet);

#pragma unroll
            for (int i = 0; i < 6; i++) s.xT[i * 32 + b] = xn[i];

            size_t base = ((size_t)g * TSTEPS + t);
            g_ll[base * BATCH + gb0 + b] = ll;
#pragma unroll
            for (int i = 0; i < 6; i++)
                g_xn[(base * 6 + i) * BATCH + gb0 + b] = xn[i];
        }
        __syncthreads();   // S9
    }
}

// ---------------- epilogue: argmax over groups + gather ----------------
__global__ void nkf_argmax(float* __restrict__ out)
{
    int idx = blockIdx.x * blockDim.x + threadIdx.x;
    const int TB = TSTEPS * BATCH;
    if (idx >= TB) return;
    float best = g_ll[idx];
    int bg = 0;
#pragma unroll
    for (int gg = 1; gg < NG; gg++) {
        float v = g_ll[(size_t)gg * TB + idx];
        if (v > best) { best = v; bg = gg; }
    }
    int t = idx / BATCH, b = idx % BATCH;
    size_t base = ((size_t)bg * TSTEPS + t);
#pragma unroll
    for (int i = 0; i < 6; i++)
        out[(size_t)idx * 6 + i] = g_xn[(base * 6 + i) * BATCH + b];
}

extern "C" void kernel_launch(void* const* d_in, const int* in_sizes, int n_in,
                              void* d_out, int out_size)
{
    (void)in_sizes; (void)n_in; (void)out_size;
    const float* z    = (const float*)d_in[0];
    const float* x0   = (const float*)d_in[1];
    const float* We1  = (const float*)d_in[2];
    const float* be1  = (const float*)d_in[3];
    const float* We2  = (const float*)d_in[4];
    const float* be2  = (const float*)d_in[5];
    const float* Wi0  = (const float*)d_in[6];
    const float* Wh0  = (const float*)d_in[7];
    const float* b0g  = (const float*)d_in[8];
    const float* Wi1  = (const float*)d_in[9];
    const float* Wh1  = (const float*)d_in[10];
    const float* b1l  = (const float*)d_in[11];
    const float* Qlog = (const float*)d_in[12];
    const float* Rlog = (const float*)d_in[13];
    float* out = (float*)d_out;

    static const size_t smem = sizeof(Smem);
    cudaFuncSetAttribute(nkf_main, cudaFuncAttributeMaxDynamicSharedMemorySize, (int)smem);

    int wtot = NG * 112 * 256;
    nkf_prep<<<(wtot + 255) / 256, 256>>>(Wi0, Wh0);
    nkf_main<<<GRIDSZ, NTHREADS, smem>>>(z, x0, We1, be1, We2, be2,
                                         Wi0, Wh0, b0g, Wi1, Wh1, b1l, Qlog, Rlog);
    int tb = TSTEPS * BATCH;
    nkf_argmax<<<(tb + 255) / 256, 256>>>(out);
}

// round 9
// speedup vs baseline: 1.1118x; 1.1118x over previous
#include <cuda_runtime.h>
#include <math.h>

#define NG      4
#define HIDN    64
#define BATCH   4096
#define TSTEPS  128
#define NB      32
#define NTHREADS 256
#define NTILES  (BATCH / NB)     // 128
#define GRIDSZ  (NG * NTILES)    // 512

typedef unsigned long long u64;

// ---------------- global scratch (allocation-free) ----------------
__device__ float g_ll[(size_t)NG * TSTEPS * BATCH];
__device__ float g_xn[(size_t)NG * TSTEPS * 6 * BATCH];

// ---------------- f32x2 helpers ----------------
__device__ __forceinline__ u64 dup2(float a) {
    u64 r; asm("mov.b64 %0, {%1, %1};" : "=l"(r) : "f"(a)); return r;
}
__device__ __forceinline__ void unpk2(u64 v, float& lo, float& hi) {
    asm("mov.b64 {%0, %1}, %2;" : "=f"(lo), "=f"(hi) : "l"(v));
}
__device__ __forceinline__ u64 fma2(u64 a, u64 b, u64 c) {
    u64 d; asm("fma.rn.f32x2 %0, %1, %2, %3;" : "=l"(d) : "l"(a), "l"(b), "l"(c));
    return d;
}

// ---------------- fast activations (EX2/RCP based, rel err ~1e-6) ----------------
__device__ __forceinline__ float sigf(float x) {
    return __fdividef(1.0f, 1.0f + __expf(-x));
}
__device__ __forceinline__ float tanh_fast(float x) {
    return 1.0f - 2.0f * __fdividef(1.0f, __expf(2.0f * x) + 1.0f);
}

// batch -> float offset in a dup'd 72-float row
__device__ __forceinline__ int doff(int b) { return 2 * b + ((b >= 16) ? 4 : 0); }

struct __align__(16) Smem {
    float We1[19 * 48];
    float be1[48];
    float We2[48 * 48];
    float be2[48];
    float W0[112 * 256];     // [k][u*4+gate]
    float b0[256];
    float W1p[68 * 16];      // [k][w*2 + half] = W1[k][w + half*8]
    float b1[16];
    float inTd[2][112 * 72]; // double-buffered dup'd rows: 0..47 e2, 48..111 h0
    float e1Td[48 * 72];     // dup'd
    float g1T[16 * 32];
    float h1T[4 * 32];
    float zsT[2][4 * 32];    // double-buffered
    float xT[6 * 32];
    float PT[36 * 32];
};

// ---- 4x4 LU (no pivot) with precomputed reciprocals ----
__device__ __forceinline__ void lu4_fact(float* M, float* id) {
    id[0] = __fdividef(1.0f, M[0]);
    M[4] *= id[0]; M[8] *= id[0]; M[12] *= id[0];
    M[5]  -= M[4]  * M[1]; M[6]  -= M[4]  * M[2]; M[7]  -= M[4]  * M[3];
    M[9]  -= M[8]  * M[1]; M[10] -= M[8]  * M[2]; M[11] -= M[8]  * M[3];
    M[13] -= M[12] * M[1]; M[14] -= M[12] * M[2]; M[15] -= M[12] * M[3];
    id[1] = __fdividef(1.0f, M[5]);
    M[9] *= id[1]; M[13] *= id[1];
    M[10] -= M[9]  * M[6]; M[11] -= M[9]  * M[7];
    M[14] -= M[13] * M[6]; M[15] -= M[13] * M[7];
    id[2] = __fdividef(1.0f, M[10]);
    M[14] *= id[2];
    M[15] -= M[14] * M[11];
    id[3] = __fdividef(1.0f, M[15]);
}
__device__ __forceinline__ void lu4_solve(const float* M, const float* id,
                                          const float* r, float* v) {
    float y0 = r[0];
    float y1 = r[1] - M[4]  * y0;
    float y2 = r[2] - M[8]  * y0 - M[9]  * y1;
    float y3 = r[3] - M[12] * y0 - M[13] * y1 - M[14] * y2;
    v[3] = y3 * id[3];
    v[2] = (y2 - M[11] * v[3]) * id[2];
    v[1] = (y1 - M[6] * v[2] - M[7] * v[3]) * id[1];
    v[0] = (y0 - M[1] * v[1] - M[2] * v[2] - M[3] * v[3]) * id[0];
}
__device__ __forceinline__ void lu4_solveT(const float* M, const float* id,
                                           const float* r, float* v) {
    float w0 = r[0] * id[0];
    float w1 = (r[1] - M[1] * w0) * id[1];
    float w2 = (r[2] - M[2] * w0 - M[6]  * w1) * id[2];
    float w3 = (r[3] - M[3] * w0 - M[7]  * w1 - M[11] * w2) * id[3];
    v[3] = w3;
    v[2] = w2 - M[14] * v[3];
    v[1] = w1 - M[9]  * v[2] - M[13] * v[3];
    v[0] = w0 - M[4]  * v[1] - M[8]  * v[2] - M[12] * v[3];
}

__global__ __launch_bounds__(NTHREADS, 1)
void nkf_main(const float* __restrict__ z,    const float* __restrict__ x0,
              const float* __restrict__ We1,  const float* __restrict__ be1,
              const float* __restrict__ We2,  const float* __restrict__ be2,
              const float* __restrict__ Wi0,  const float* __restrict__ Wh0,
              const float* __restrict__ b0g,  const float* __restrict__ Wi1,
              const float* __restrict__ Wh1,  const float* __restrict__ b1l,
              const float* __restrict__ Qlog, const float* __restrict__ Rlog)
{
    extern __shared__ __align__(16) char smem_raw[];
    Smem& s = *reinterpret_cast<Smem*>(smem_raw);

    const int tid  = threadIdx.x;
    const int g    = blockIdx.x / NTILES;
    const int tile = blockIdx.x % NTILES;
    const int gb0  = tile * NB;
    const int b    = tid & 31;
    const int w    = tid >> 5;
    const int cg   = tid >> 3;   // 0..31 (column group: 8 cols = 2 units)
    const int bg   = tid & 7;    // 0..7  (batch group: 4 batch)

    // ---------------- stage weights ----------------
    for (int i = tid; i < 19 * 48; i += NTHREADS) s.We1[i] = We1[i];
    for (int i = tid; i < 48;      i += NTHREADS) { s.be1[i] = be1[i]; s.be2[i] = be2[i]; }
    for (int i = tid; i < 48 * 48; i += NTHREADS) s.We2[i] = We2[i];
    for (int i = tid; i < 112 * 256; i += NTHREADS) {
        int k = i >> 8, col = i & 255;
        int u = col >> 2, gate = col & 3;
        int sc = gate * 64 + u;
        s.W0[i] = (k < 48) ? Wi0[(g * 48 + k) * 256 + sc]
                           : Wh0[(g * 64 + (k - 48)) * 256 + sc];
    }
    for (int i = tid; i < 256; i += NTHREADS) {
        int u = i >> 2, gate = i & 3;
        s.b0[i] = b0g[g * 256 + gate * 64 + u];
    }
    for (int i = tid; i < 68 * 16; i += NTHREADS) {
        int k = i >> 4, j = i & 15;
        int ww = j >> 1, half = j & 1;
        int col = ww + half * 8;
        s.W1p[i] = (k < 64) ? Wi1[(g * 64 + k) * 16 + col]
                            : Wh1[(g * 4 + (k - 64)) * 16 + col];
    }
    if (tid < 16) s.b1[tid] = b1l[g * 16 + tid];

    // noise diagonals (registers)
    float qd[6], rd[4];
#pragma unroll
    for (int i = 0; i < 6; i++) qd[i] = expf(Qlog[g * 6 + i]);
#pragma unroll
    for (int i = 0; i < 4; i++) rd[i] = expf(Rlog[i]);

    // ---------------- init state ----------------
    for (int i = tid; i < 6 * NB; i += NTHREADS) {
        int r = i >> 5, bb = i & 31;
        s.xT[i] = x0[(gb0 + bb) * 6 + r];
    }
    for (int i = tid; i < 36 * NB; i += NTHREADS) {
        int rc = i >> 5;
        s.PT[i] = (rc % 7 == 0) ? 1000.0f : 0.0f;
    }
    for (int i = tid; i < 2 * 112 * 72; i += NTHREADS) s.inTd[0][i] = 0.0f;
    for (int i = tid; i < 4 * 32;       i += NTHREADS) s.h1T[i] = 0.0f;
    if (tid < 128) {
        int bb = tid >> 2, c = tid & 3;
        s.zsT[0][c * 32 + bb] = z[((gb0 + bb) * TSTEPS + 0) * 4 + c];
    }
    __syncthreads();

    const int abase = (bg < 4) ? bg * 8 : bg * 8 + 4;
    float c0r[8] = {0, 0, 0, 0, 0, 0, 0, 0};   // LSTM0 cell: 2 units x 4 batch
    float c1r[4] = {0, 0, 0, 0};               // LSTM1 cell (warp0 only)

    for (int t = 0; t < TSTEPS; ++t) {
        const float* zcur = s.zsT[t & 1];
        float* bufc = s.inTd[t & 1];
        float* bufn = s.inTd[(t + 1) & 1];

        // ---- feats (per-thread registers) + e1 (all 256 threads) ----
        {
            float f[19];
#pragma unroll
            for (int c = 0; c < 4; c++) f[c] = zcur[c * 32 + b];
            float xv[6];
#pragma unroll
            for (int i = 0; i < 6; i++) { xv[i] = s.xT[i * 32 + b]; f[4 + i] = xv[i]; }
            float n1 = 0.0f;
#pragma unroll
            for (int c = 0; c < 4; c++) {
                float in = f[c] - xv[c];
                f[10 + c] = in;
                n1 += in * in;
            }
            f[14] = sqrtf(fmaxf(n1, 0.0f));
            f[15] = sqrtf(fmaxf(xv[0]*xv[0] + xv[1]*xv[1] + xv[2]*xv[2], 0.0f));
            f[16] = sqrtf(fmaxf(xv[3]*xv[3] + xv[4]*xv[4] + xv[5]*xv[5], 0.0f));
            f[17] = (float)t / 100.0f;
            f[18] = 1.0f;

            float acc[6];
#pragma unroll
            for (int j = 0; j < 6; j++) acc[j] = s.be1[w * 6 + j];
#pragma unroll
            for (int k = 0; k < 19; k++) {
#pragma unroll
                for (int j = 0; j < 6; j++) acc[j] += f[k] * s.We1[k * 48 + w * 6 + j];
            }
            int o = doff(b);
#pragma unroll
            for (int j = 0; j < 6; j++)
                *(u64*)(s.e1Td + (w * 6 + j) * 72 + o) = dup2(fmaxf(acc[j], 0.0f));
        }
        __syncthreads();   // B1: e1 ready

        // ---- e2 (threads 0-191, packed) -> bufc rows 0..47 ----
        if (tid < 192) {
            int cp  = tid >> 3;
            int bg2 = tid & 7;
            int ab  = (bg2 < 4) ? bg2 * 8 : bg2 * 8 + 4;
            u64 bias = *(const u64*)(s.be2 + cp * 2);
            u64 acc0 = bias, acc1 = bias, acc2 = bias, acc3 = bias;
            const float* wp = s.We2 + cp * 2;
            const float* ap = s.e1Td + ab;
#pragma unroll 4
            for (int k = 0; k < 48; k++) {
                u64 wv = *(const u64*)(wp);
                ulonglong2 p01 = *(const ulonglong2*)(ap);
                ulonglong2 p23 = *(const ulonglong2*)(ap + 4);
                acc0 = fma2(wv, p01.x, acc0);
                acc1 = fma2(wv, p01.y, acc1);
                acc2 = fma2(wv, p23.x, acc2);
                acc3 = fma2(wv, p23.y, acc3);
                wp += 48; ap += 72;
            }
            u64 av[4] = {acc0, acc1, acc2, acc3};
#pragma unroll
            for (int m = 0; m < 4; m++) {
                int bb = bg2 * 4 + m, o = doff(bb);
                float lo, hi; unpk2(av[m], lo, hi);
                *(u64*)(bufc + (2 * cp)     * 72 + o) = dup2(fmaxf(lo, 0.0f));
                *(u64*)(bufc + (2 * cp + 1) * 72 + o) = dup2(fmaxf(hi, 0.0f));
            }
        }
        __syncthreads();   // B2: bufc complete (e2 + h0 from prev pointwise)

        // ---- LSTM0 matvec + fused pointwise (no barrier between!) ----
        {
            u64 a[16];
#pragma unroll
            for (int p = 0; p < 4; p++) {
                u64 bias = *(const u64*)(s.b0 + cg * 8 + p * 2);
#pragma unroll
                for (int m = 0; m < 4; m++) a[p * 4 + m] = bias;
            }
            const float* wp = s.W0 + cg * 8;
            const float* ap = bufc + abase;
#pragma unroll 4
            for (int k = 0; k < 112; k++) {
                ulonglong2 w01 = *(const ulonglong2*)(wp);
                ulonglong2 w23 = *(const ulonglong2*)(wp + 4);
                ulonglong2 p01 = *(const ulonglong2*)(ap);
                ulonglong2 p23 = *(const ulonglong2*)(ap + 4);
                a[0]  = fma2(w01.x, p01.x, a[0]);
                a[1]  = fma2(w01.x, p01.y, a[1]);
                a[2]  = fma2(w01.x, p23.x, a[2]);
                a[3]  = fma2(w01.x, p23.y, a[3]);
                a[4]  = fma2(w01.y, p01.x, a[4]);
                a[5]  = fma2(w01.y, p01.y, a[5]);
                a[6]  = fma2(w01.y, p23.x, a[6]);
                a[7]  = fma2(w01.y, p23.y, a[7]);
                a[8]  = fma2(w23.x, p01.x, a[8]);
                a[9]  = fma2(w23.x, p01.y, a[9]);
                a[10] = fma2(w23.x, p23.x, a[10]);
                a[11] = fma2(w23.x, p23.y, a[11]);
                a[12] = fma2(w23.y, p01.x, a[12]);
                a[13] = fma2(w23.y, p01.y, a[13]);
                a[14] = fma2(w23.y, p23.x, a[14]);
                a[15] = fma2(w23.y, p23.y, a[15]);
                wp += 256; ap += 72;
            }
            // pointwise: writes h0 into bufn rows 48..111 (other warps may still
            // be reading bufc — different buffer, no race)
#pragma unroll
            for (int uu = 0; uu < 2; uu++) {
                int u = cg * 2 + uu;
#pragma unroll
                for (int m = 0; m < 4; m++) {
                    int bb = bg * 4 + m;
                    float gi, gf, gg, go;
                    unpk2(a[(uu * 2 + 0) * 4 + m], gi, gf);
                    unpk2(a[(uu * 2 + 1) * 4 + m], gg, go);
                    float cn = sigf(gf) * c0r[uu * 4 + m] + sigf(gi) * tanh_fast(gg);
                    float hn = sigf(go) * tanh_fast(cn);
                    c0r[uu * 4 + m] = cn;
                    *(u64*)(bufn + (48 + u) * 72 + doff(bb)) = dup2(hn);
                }
            }
        }
        __syncthreads();   // B3: h0n ready

        // ---- LSTM1 matvec (all 256, packed pairs (w, w+8)) ----
        {
            int o2 = doff(b);
            u64 acc = *(const u64*)(s.b1 + 0) ;  // placeholder init below
            // bias pair (b1[w], b1[w+8]) is not adjacent; build it
            float blo = s.b1[w], bhi = s.b1[w + 8];
            u64 accp; asm("mov.b64 %0, {%1, %2};" : "=l"(accp) : "f"(blo), "f"(bhi));
            (void)acc;
            const float* hp = bufn + 48 * 72 + o2;
            const float* wp = s.W1p + w * 2;
#pragma unroll 4
            for (int k = 0; k < 64; k++) {
                u64 hv = *(const u64*)(hp);          // dup'd pair (h, h)
                u64 wv = *(const u64*)(wp);          // (W1[k][w], W1[k][w+8])
                accp = fma2(hv, wv, accp);
                hp += 72; wp += 16;
            }
            // recurrent part: h1 prev (from h1T, scalar dup)
#pragma unroll
            for (int k = 0; k < 4; k++) {
                u64 hv = dup2(s.h1T[k * 32 + b]);
                u64 wv = *(const u64*)(s.W1p + (64 + k) * 16 + w * 2);
                accp = fma2(hv, wv, accp);
            }
            float a0, a1; unpk2(accp, a0, a1);
            s.g1T[w * 32 + b] = a0;
            s.g1T[(w + 8) * 32 + b] = a1;
        }
        __syncthreads();   // B4: g1 ready

        // ---- phase F: warp0 = LSTM1 pointwise + Kalman; warps 4-7 = z prefetch ----
        if (tid >= 128) {
            if (t + 1 < TSTEPS) {
                int q = tid - 128, bb = q >> 2, c = q & 3;
                s.zsT[(t + 1) & 1][c * 32 + bb] = z[((gb0 + bb) * TSTEPS + (t + 1)) * 4 + c];
            }
        } else if (tid < 32) {
            float h1v[4];
#pragma unroll
            for (int u = 0; u < 4; u++) {
                float gi = s.g1T[(0 + u)  * 32 + b];
                float gf = s.g1T[(4 + u)  * 32 + b];
                float gg = s.g1T[(8 + u)  * 32 + b];
                float go = s.g1T[(12 + u) * 32 + b];
                float cn = sigf(gf) * c1r[u] + sigf(gi) * tanh_fast(gg);
                c1r[u] = cn;
                h1v[u] = sigf(go) * tanh_fast(cn);
                s.h1T[u * 32 + b] = h1v[u];
            }
            float logp = h1v[0], a0v = h1v[1], a1v = h1v[2], a2v = h1v[3];

            float xv[6];
#pragma unroll
            for (int i = 0; i < 6; i++) xv[i] = s.xT[i * 32 + b];
            float xp[6];
            xp[0] = xv[0] + xv[3] + 0.5f * a0v;
            xp[1] = xv[1] + xv[4] + 0.5f * a1v;
            xp[2] = xv[2] + xv[5] + 0.5f * a2v;
            xp[3] = xv[3] + a0v;
            xp[4] = xv[4] + a1v;
            xp[5] = xv[5] + a2v;

            // P_pred = F P F^T + Q
            float Pp[36];
#pragma unroll
            for (int i = 0; i < 6; i++) {
#pragma unroll
                for (int j = 0; j < 6; j++) {
                    float v = s.PT[(i * 6 + j) * 32 + b];
                    if (i < 3) v += s.PT[((i + 3) * 6 + j) * 32 + b];
                    if (j < 3) {
                        v += s.PT[(i * 6 + j + 3) * 32 + b];
                        if (i < 3) v += s.PT[((i + 3) * 6 + j + 3) * 32 + b];
                    }
                    if (i == j) v += qd[i];
                    Pp[i * 6 + j] = v;
                }
            }

            float y[4];
#pragma unroll
            for (int c = 0; c < 4; c++) y[c] = zcur[c * 32 + b] - xp[c];

            float M[16];
#pragma unroll
            for (int r = 0; r < 4; r++)
#pragma unroll
                for (int c = 0; c < 4; c++)
                    M[r * 4 + c] = Pp[r * 6 + c] + ((r == c) ? rd[r] : 0.0f);
            float id[4];
            lu4_fact(M, id);
            float logdet = __logf(fabsf(M[0] * M[5] * M[10] * M[15]));

            float siy[4];
            lu4_solve(M, id, y, siy);

            float K[24];
#pragma unroll
            for (int i = 0; i < 6; i++) {
                float rhs[4] = { Pp[i * 6 + 0], Pp[i * 6 + 1], Pp[i * 6 + 2], Pp[i * 6 + 3] };
                lu4_solveT(M, id, rhs, &K[i * 4]);
            }

            float xn[6];
#pragma unroll
            for (int i = 0; i < 6; i++)
                xn[i] = xp[i] + K[i*4+0]*y[0] + K[i*4+1]*y[1] + K[i*4+2]*y[2] + K[i*4+3]*y[3];

#pragma unroll
            for (int i = 0; i < 6; i++) {
#pragma unroll
                for (int j = 0; j < 6; j++) {
                    float v = Pp[i * 6 + j]
                            - K[i*4+0] * Pp[0*6+j]
                            - K[i*4+1] * Pp[1*6+j]
                            - K[i*4+2] * Pp[2*6+j]
                            - K[i*4+3] * Pp[3*6+j];
                    s.PT[(i * 6 + j) * 32 + b] = v;
                }
            }

            float quad = y[0]*siy[0] + y[1]*siy[1] + y[2]*siy[2] + y[3]*siy[3];
            float ll = logp - 0.5f * (quad + logdet);

#pragma unroll
            for (int i = 0; i < 6; i++) s.xT[i * 32 + b] = xn[i];

            size_t base = ((size_t)g * TSTEPS + t);
            g_ll[base * BATCH + gb0 + b] = ll;
#pragma unroll
            for (int i = 0; i < 6; i++)
                g_xn[(base * 6 + i) * BATCH + gb0 + b] = xn[i];
        }
        __syncthreads();   // B5
    }
}

// ---------------- epilogue: argmax over groups + gather ----------------
__global__ void nkf_argmax(float* __restrict__ out)
{
    int idx = blockIdx.x * blockDim.x + threadIdx.x;
    const int TB = TSTEPS * BATCH;
    if (idx >= TB) return;
    float best = g_ll[idx];
    int bg = 0;
#pragma unroll
    for (int gg = 1; gg < NG; gg++) {
        float v = g_ll[(size_t)gg * TB + idx];
        if (v > best) { best = v; bg = gg; }
    }
    int t = idx / BATCH, b = idx % BATCH;
    size_t base = ((size_t)bg * TSTEPS + t);
#pragma unroll
    for (int i = 0; i < 6; i++)
        out[(size_t)idx * 6 + i] = g_xn[(base * 6 + i) * BATCH + b];
}

extern "C" void kernel_launch(void* const* d_in, const int* in_sizes, int n_in,
                              void* d_out, int out_size)
{
    (void)in_sizes; (void)n_in; (void)out_size;
    const float* z    = (const float*)d_in[0];
    const float* x0   = (const float*)d_in[1];
    const float* We1  = (const float*)d_in[2];
    const float* be1  = (const float*)d_in[3];
    const float* We2  = (const float*)d_in[4];
    const float* be2  = (const float*)d_in[5];
    const float* Wi0  = (const float*)d_in[6];
    const float* Wh0  = (const float*)d_in[7];
    const float* b0g  = (const float*)d_in[8];
    const float* Wi1  = (const float*)d_in[9];
    const float* Wh1  = (const float*)d_in[10];
    const float* b1l  = (const float*)d_in[11];
    const float* Qlog = (const float*)d_in[12];
    const float* Rlog = (const float*)d_in[13];
    float* out = (float*)d_out;

    static const size_t smem = sizeof(Smem);
    cudaFuncSetAttribute(nkf_main, cudaFuncAttributeMaxDynamicSharedMemorySize, (int)smem);

    nkf_main<<<GRIDSZ, NTHREADS, smem>>>(z, x0, We1, be1, We2, be2,
                                         Wi0, Wh0, b0g, Wi1, Wh1, b1l, Qlog, Rlog);
    int tb = TSTEPS * BATCH;
    nkf_argmax<<<(tb + 255) / 256, 256>>>(out);
}